// round 1
// baseline (speedup 1.0000x reference)
#include <cuda_runtime.h>

#define NH   16
#define Dh   64
#define Lq   1024
#define Bq   4
#define Eq   1024
#define BH   (Bq*NH)        // 64
#define MROWS (Lq*Bq)       // 4096

// Scratch (device globals; no runtime allocation allowed)
__device__ float g_q[BH*Lq*Dh];        // 16 MB  (BH, L, D), pre-scaled by 1/8
__device__ float g_k[BH*Lq*Dh];        // 16 MB
__device__ float g_v[BH*Lq*Dh];        // 16 MB
__device__ float g_s[BH*Lq*Lq];        // 256 MB  scores, then P in-place
__device__ float g_qe[BH*Lq*Lq];       // 256 MB  relative-pos logits
__device__ float g_ctx[MROWS*Eq];      // 16 MB  (L,B,E)

// ---------------------------------------------------------------------------
// 128x128 tile SGEMM mainloop: C += A(MxK) * B^T  (B is N x K row-major)
// blockDim = 256. A,B pre-offset to tile origin. K % 8 == 0, lda/ldb % 4 == 0.
// ---------------------------------------------------------------------------
__device__ __forceinline__ void gemm_nt_128(const float* __restrict__ A,
                                            const float* __restrict__ B,
                                            int K, int lda, int ldb,
                                            float acc[8][8])
{
    __shared__ float As[8][128];
    __shared__ float Bs[8][128];
    const int tid   = threadIdx.x;
    const int a_row = tid >> 1;          // 0..127
    const int a_col = (tid & 1) * 4;     // 0 or 4
    const int tx    = tid & 15;          // n frag
    const int ty    = tid >> 4;          // m frag

    for (int k0 = 0; k0 < K; k0 += 8) {
        float4 av = *(const float4*)(A + (size_t)a_row * lda + k0 + a_col);
        float4 bv = *(const float4*)(B + (size_t)a_row * ldb + k0 + a_col);
        __syncthreads();
        As[a_col+0][a_row] = av.x; As[a_col+1][a_row] = av.y;
        As[a_col+2][a_row] = av.z; As[a_col+3][a_row] = av.w;
        Bs[a_col+0][a_row] = bv.x; Bs[a_col+1][a_row] = bv.y;
        Bs[a_col+2][a_row] = bv.z; Bs[a_col+3][a_row] = bv.w;
        __syncthreads();
        #pragma unroll
        for (int kk = 0; kk < 8; kk++) {
            float4 a0 = *(const float4*)&As[kk][ty*8];
            float4 a1 = *(const float4*)&As[kk][ty*8+4];
            float4 b0 = *(const float4*)&Bs[kk][tx*8];
            float4 b1 = *(const float4*)&Bs[kk][tx*8+4];
            float a[8] = {a0.x,a0.y,a0.z,a0.w,a1.x,a1.y,a1.z,a1.w};
            float b[8] = {b0.x,b0.y,b0.z,b0.w,b1.x,b1.y,b1.z,b1.w};
            #pragma unroll
            for (int i = 0; i < 8; i++)
                #pragma unroll
                for (int j = 0; j < 8; j++)
                    acc[i][j] += a[i] * b[j];
        }
    }
}

// ---------------------------------------------------------------------------
// 1) QKV projection: qkv = query(4096x1024) @ W^T(1024->3072) + bias
//    scatter into g_q (scaled 1/8), g_k, g_v in (BH, L, D) layout
// ---------------------------------------------------------------------------
__global__ __launch_bounds__(256) void k_qkv(const float* __restrict__ query,
                                             const float* __restrict__ W,
                                             const float* __restrict__ bias)
{
    const int m0 = blockIdx.y * 128;
    const int n0 = blockIdx.x * 128;
    float acc[8][8] = {};
    gemm_nt_128(query + (size_t)m0 * Eq, W + (size_t)n0 * Eq, Eq, Eq, Eq, acc);

    const int tx = threadIdx.x & 15, ty = threadIdx.x >> 4;
    #pragma unroll
    for (int i = 0; i < 8; i++) {
        const int m = m0 + ty*8 + i;
        const int l = m >> 2;            // row = l*B + b
        const int b = m & 3;
        #pragma unroll
        for (int j = 0; j < 8; j++) {
            const int n   = n0 + tx*8 + j;
            const float v = acc[i][j] + bias[n];
            const int sec = n >> 10;     // 0:q 1:k 2:v
            const int e   = n & 1023;
            const int h   = e >> 6;
            const int d   = e & 63;
            const int idx = ((b*NH + h)*Lq + l)*Dh + d;
            if      (sec == 0) g_q[idx] = v * 0.125f;   // 1/sqrt(64)
            else if (sec == 1) g_k[idx] = v;
            else               g_v[idx] = v;
        }
    }
}

// ---------------------------------------------------------------------------
// 2/3) Batched scores: out[bh] = Q[bh] @ Bmat^T
//      use_er==0: Bmat = g_k[bh], out = g_s ; use_er==1: Bmat = er, out = g_qe
// ---------------------------------------------------------------------------
__global__ __launch_bounds__(256) void k_scores(const float* __restrict__ er,
                                                int use_er)
{
    const int bh = blockIdx.z;
    const int m0 = blockIdx.y * 128;
    const int n0 = blockIdx.x * 128;
    const float* A = g_q + (size_t)bh*Lq*Dh + (size_t)m0*Dh;
    const float* B = use_er ? (er + (size_t)n0*Dh)
                            : (g_k + (size_t)bh*Lq*Dh + (size_t)n0*Dh);
    float acc[8][8] = {};
    gemm_nt_128(A, B, Dh, Dh, Dh, acc);

    float* C = (use_er ? g_qe : g_s) + (size_t)bh*Lq*Lq;
    const int tx = threadIdx.x & 15, ty = threadIdx.x >> 4;
    #pragma unroll
    for (int i = 0; i < 8; i++)
        #pragma unroll
        for (int j = 0; j < 8; j++)
            C[(size_t)(m0 + ty*8 + i)*Lq + (n0 + tx*8 + j)] = acc[i][j];
}

// ---------------------------------------------------------------------------
// 4) Softmax over rows of (S + skew(QE)); writes P in-place into g_s.
//    srel[l,m] = qe[l, m + (L-1) - l] for m <= l, else 0.
// ---------------------------------------------------------------------------
__global__ __launch_bounds__(256) void k_softmax()
{
    const int l  = blockIdx.x;
    const int bh = blockIdx.y;
    float* __restrict__ srow       = g_s  + ((size_t)bh*Lq + l)*Lq;
    const float* __restrict__ qrow = g_qe + ((size_t)bh*Lq + l)*Lq;
    const int tid = threadIdx.x;

    float vals[4];
    float mx = -3.4e38f;
    #pragma unroll
    for (int i = 0; i < 4; i++) {
        const int m = tid + i*256;
        float v = srow[m];
        if (m <= l) v += qrow[m + (Lq-1) - l];
        vals[i] = v;
        mx = fmaxf(mx, v);
    }
    __shared__ float red[256];
    red[tid] = mx; __syncthreads();
    for (int s = 128; s > 0; s >>= 1) {
        if (tid < s) red[tid] = fmaxf(red[tid], red[tid+s]);
        __syncthreads();
    }
    mx = red[0];
    __syncthreads();

    float sum = 0.f;
    #pragma unroll
    for (int i = 0; i < 4; i++) { vals[i] = __expf(vals[i] - mx); sum += vals[i]; }
    red[tid] = sum; __syncthreads();
    for (int s = 128; s > 0; s >>= 1) {
        if (tid < s) red[tid] += red[tid+s];
        __syncthreads();
    }
    const float inv = 1.0f / red[0];
    #pragma unroll
    for (int i = 0; i < 4; i++) srow[tid + i*256] = vals[i] * inv;
}

// ---------------------------------------------------------------------------
// 5) ctx = P(1024x1024) @ V(1024x64) per batch; write to (L,B,E) layout
//    tile 128(m) x 64(n), K-step 16, 256 threads, micro 4x8
// ---------------------------------------------------------------------------
__global__ __launch_bounds__(256) void k_pv()
{
    const int bh = blockIdx.y;
    const int m0 = blockIdx.x * 128;
    const float* __restrict__ P = g_s + (size_t)bh*Lq*Lq;
    const float* __restrict__ V = g_v + (size_t)bh*Lq*Dh;

    __shared__ float Ps[16][128];
    __shared__ float Vs[16][64];
    const int tid = threadIdx.x;
    const int pr = tid >> 2;            // 0..63
    const int pc = (tid & 3) * 4;       // 0..12
    const int vr = tid >> 4;            // 0..15
    const int vc = (tid & 15) * 4;      // 0..60
    const int tx = tid & 7;             // n: 8 groups of 8
    const int ty = tid >> 3;            // m: 32 groups of 4

    float acc[4][8] = {};
    for (int k0 = 0; k0 < Lq; k0 += 16) {
        float4 p0 = *(const float4*)&P[(size_t)(m0+pr)     *Lq + k0 + pc];
        float4 p1 = *(const float4*)&P[(size_t)(m0+pr+64)  *Lq + k0 + pc];
        float4 vv = *(const float4*)&V[(size_t)(k0+vr)*Dh + vc];
        __syncthreads();
        Ps[pc+0][pr]    = p0.x; Ps[pc+1][pr]    = p0.y;
        Ps[pc+2][pr]    = p0.z; Ps[pc+3][pr]    = p0.w;
        Ps[pc+0][pr+64] = p1.x; Ps[pc+1][pr+64] = p1.y;
        Ps[pc+2][pr+64] = p1.z; Ps[pc+3][pr+64] = p1.w;
        *(float4*)&Vs[vr][vc] = vv;
        __syncthreads();
        #pragma unroll
        for (int kk = 0; kk < 16; kk++) {
            float4 av = *(const float4*)&Ps[kk][ty*4];
            float4 b0 = *(const float4*)&Vs[kk][tx*8];
            float4 b1 = *(const float4*)&Vs[kk][tx*8+4];
            float a[4] = {av.x, av.y, av.z, av.w};
            float b[8] = {b0.x,b0.y,b0.z,b0.w,b1.x,b1.y,b1.z,b1.w};
            #pragma unroll
            for (int i = 0; i < 4; i++)
                #pragma unroll
                for (int j = 0; j < 8; j++)
                    acc[i][j] += a[i] * b[j];
        }
    }
    const int b = bh >> 4, h = bh & 15;
    #pragma unroll
    for (int i = 0; i < 4; i++) {
        const int l = m0 + ty*4 + i;
        #pragma unroll
        for (int j = 0; j < 8; j++) {
            const int d = tx*8 + j;
            g_ctx[(size_t)l*(Bq*Eq) + b*Eq + h*Dh + d] = acc[i][j];
        }
    }
}

// ---------------------------------------------------------------------------
// 6) out = ctx(4096x1024) @ Wout^T + bias  -> d_out (L,B,E)
// ---------------------------------------------------------------------------
__global__ __launch_bounds__(256) void k_outproj(const float* __restrict__ W,
                                                 const float* __restrict__ bias,
                                                 float* __restrict__ out)
{
    const int m0 = blockIdx.y * 128;
    const int n0 = blockIdx.x * 128;
    float acc[8][8] = {};
    gemm_nt_128(g_ctx + (size_t)m0 * Eq, W + (size_t)n0 * Eq, Eq, Eq, Eq, acc);

    const int tx = threadIdx.x & 15, ty = threadIdx.x >> 4;
    #pragma unroll
    for (int i = 0; i < 8; i++) {
        const int m = m0 + ty*8 + i;
        #pragma unroll
        for (int j = 0; j < 8; j++) {
            const int n = n0 + tx*8 + j;
            out[(size_t)m*Eq + n] = acc[i][j] + bias[n];
        }
    }
}

// ---------------------------------------------------------------------------
extern "C" void kernel_launch(void* const* d_in, const int* in_sizes, int n_in,
                              void* d_out, int out_size)
{
    const float* query  = (const float*)d_in[0];   // (L,B,E)
    const float* relpos = (const float*)d_in[1];   // (L,D)
    const float* w_in   = (const float*)d_in[2];   // (3E,E)
    const float* b_in   = (const float*)d_in[3];   // (3E,)
    const float* w_out  = (const float*)d_in[4];   // (E,E)
    const float* b_out  = (const float*)d_in[5];   // (E,)
    float* out = (float*)d_out;

    dim3 blk(256);
    k_qkv    <<<dim3(24, 32),    blk>>>(query, w_in, b_in);
    k_scores <<<dim3(8, 8, BH),  blk>>>(relpos, 0);   // S  = Q K^T
    k_scores <<<dim3(8, 8, BH),  blk>>>(relpos, 1);   // QE = Q ER^T
    k_softmax<<<dim3(Lq, BH),    256>>>();
    k_pv     <<<dim3(8, BH),     blk>>>();
    k_outproj<<<dim3(8, 32),     blk>>>(w_out, b_out, out);
}

// round 3
// speedup vs baseline: 2.4254x; 2.4254x over previous
#include <cuda_runtime.h>
#include <cuda_bf16.h>
#include <stdint.h>

#define NH 16
#define Dh 64
#define Lq 1024
#define Bq 4
#define Eq 1024
#define BH 64

// ---- scratch (device globals) ----
__device__ float g_q[BH*Lq*Dh];          // (BH,L,D), q pre-scaled by 1/8
__device__ float g_k[BH*Lq*Dh];          // (BH,L,D)
__device__ float g_v[BH*Lq*Dh];          // (BH,D,L)  TRANSPOSED for PV GEMM
__device__ float g_s[(size_t)BH*Lq*Lq];  // scores -> P in place
__device__ float g_qe[(size_t)BH*Lq*Lq]; // relpos logits
__device__ float g_ctx[Lq*Bq*Eq];        // (L,B,E)

#define SWZ64(x) ((x) ^ (((x) >> 3) & 0x30))

__device__ __forceinline__ void ldsm4(uint32_t (&r)[4], uint32_t addr) {
    asm volatile("ldmatrix.sync.aligned.m8n8.x4.shared.b16 {%0,%1,%2,%3}, [%4];"
                 : "=r"(r[0]), "=r"(r[1]), "=r"(r[2]), "=r"(r[3]) : "r"(addr));
}
__device__ __forceinline__ void mma_bf16(float (&d)[4], const uint32_t (&a)[4],
                                         uint32_t b0, uint32_t b1) {
    asm volatile("mma.sync.aligned.m16n8k16.row.col.f32.bf16.bf16.f32 "
                 "{%0,%1,%2,%3}, {%4,%5,%6,%7}, {%8,%9}, {%0,%1,%2,%3};"
                 : "+f"(d[0]), "+f"(d[1]), "+f"(d[2]), "+f"(d[3])
                 : "r"(a[0]), "r"(a[1]), "r"(a[2]), "r"(a[3]), "r"(b0), "r"(b1));
}
__device__ __forceinline__ void split_bf16(float4 v, uint2& hi, uint2& lo) {
    __nv_bfloat162 h0 = __floats2bfloat162_rn(v.x, v.y);
    __nv_bfloat162 h1 = __floats2bfloat162_rn(v.z, v.w);
    __nv_bfloat162 l0 = __floats2bfloat162_rn(v.x - __low2float(h0),  v.y - __high2float(h0));
    __nv_bfloat162 l1 = __floats2bfloat162_rn(v.z - __low2float(h1),  v.w - __high2float(h1));
    hi = make_uint2(*(uint32_t*)&h0, *(uint32_t*)&h1);
    lo = make_uint2(*(uint32_t*)&l0, *(uint32_t*)&l1);
}

// ---------------------------------------------------------------------------
// C(128 x NT) = A(128 x K) * B(NT x K)^T, fp32 in/out, bf16 split-x3 HMMA.
// 256 threads, warp grid 2(m) x 4(n). K % 32 == 0, lda/ldb % 4 == 0.
// Static smem: A_hi[128x32] A_lo B_hi[NTx32] B_lo (bf16, SW64 swizzled).
// ---------------------------------------------------------------------------
template<int NT, class Epi>
__device__ __forceinline__ void mm_main(const float* __restrict__ A, int lda,
                                        const float* __restrict__ B, int ldb,
                                        int K, Epi epi)
{
    constexpr int WN   = NT / 4;     // 32 or 16
    constexpr int NTN8 = WN / 8;     // 4 or 2
    constexpr int NB16 = WN / 16;    // 2 or 1
    constexpr int BI   = NT / 32;    // B-convert iterations

    __shared__ __align__(1024) char smb[16384 + 2 * NT * 64];
    const uint32_t su   = (uint32_t)__cvta_generic_to_shared(smb);
    const uint32_t suA  = su;
    const uint32_t suAl = su + 8192;
    const uint32_t suB  = su + 16384;
    const uint32_t suBl = su + 16384 + NT * 64;

    const int tid  = threadIdx.x;
    const int lane = tid & 31, w = tid >> 5;
    const int m_base = (w & 1) * 64;
    const int n_base = (w >> 1) * WN;

    float acc[4][NTN8][4];
    #pragma unroll
    for (int i = 0; i < 4; i++)
        #pragma unroll
        for (int j = 0; j < NTN8; j++)
            #pragma unroll
            for (int q = 0; q < 4; q++) acc[i][j][q] = 0.f;

    const uint32_t a_row = lane & 15;
    const uint32_t a_k8  = (lane >> 4) * 8;
    const uint32_t b_row = (lane & 7) + ((lane >> 4) & 1) * 8;
    const uint32_t b_k8  = ((lane >> 3) & 1) * 8;

    for (int kb = 0; kb < K; kb += 32) {
        // global loads (prefetch before the barrier)
        float4 va[4], vb[BI];
        #pragma unroll
        for (int i = 0; i < 4; i++) {
            int qd = tid + i * 256;
            int r = qd >> 3, c = (qd & 7) * 4;
            va[i] = *(const float4*)(A + (size_t)r * lda + kb + c);
        }
        #pragma unroll
        for (int i = 0; i < BI; i++) {
            int qd = tid + i * 256;
            int r = qd >> 3, c = (qd & 7) * 4;
            vb[i] = *(const float4*)(B + (size_t)r * ldb + kb + c);
        }
        __syncthreads();   // previous iteration's consumers done
        #pragma unroll
        for (int i = 0; i < 4; i++) {
            int qd = tid + i * 256;
            int r = qd >> 3, c = (qd & 7) * 4;
            uint2 hi, lo; split_bf16(va[i], hi, lo);
            uint32_t off = SWZ64((uint32_t)(r * 64 + c * 2));
            *(uint2*)(smb + off)        = hi;
            *(uint2*)(smb + 8192 + off) = lo;
        }
        #pragma unroll
        for (int i = 0; i < BI; i++) {
            int qd = tid + i * 256;
            int r = qd >> 3, c = (qd & 7) * 4;
            uint2 hi, lo; split_bf16(vb[i], hi, lo);
            uint32_t off = SWZ64((uint32_t)(r * 64 + c * 2));
            *(uint2*)(smb + 16384 + off)           = hi;
            *(uint2*)(smb + 16384 + NT * 64 + off) = lo;
        }
        __syncthreads();

        #pragma unroll
        for (int kc = 0; kc < 2; kc++) {
            uint32_t ah[4][4], al[4][4];
            #pragma unroll
            for (int mt = 0; mt < 4; mt++) {
                uint32_t off = (uint32_t)((m_base + mt * 16 + a_row) * 64
                                          + (kc * 16 + a_k8) * 2);
                ldsm4(ah[mt], suA  + SWZ64(off));
                ldsm4(al[mt], suAl + SWZ64(off));
            }
            uint32_t bh[NB16][4], bl[NB16][4];
            #pragma unroll
            for (int nb = 0; nb < NB16; nb++) {
                uint32_t off = (uint32_t)((n_base + nb * 16 + b_row) * 64
                                          + (kc * 16 + b_k8) * 2);
                ldsm4(bh[nb], suB  + SWZ64(off));
                ldsm4(bl[nb], suBl + SWZ64(off));
            }
            #pragma unroll
            for (int mt = 0; mt < 4; mt++)
                #pragma unroll
                for (int nt = 0; nt < NTN8; nt++) {
                    uint32_t b0h = bh[nt >> 1][(nt & 1) * 2];
                    uint32_t b1h = bh[nt >> 1][(nt & 1) * 2 + 1];
                    uint32_t b0l = bl[nt >> 1][(nt & 1) * 2];
                    uint32_t b1l = bl[nt >> 1][(nt & 1) * 2 + 1];
                    mma_bf16(acc[mt][nt], ah[mt], b0h, b1h);  // hi*hi
                    mma_bf16(acc[mt][nt], ah[mt], b0l, b1l);  // hi*lo
                    mma_bf16(acc[mt][nt], al[mt], b0h, b1h);  // lo*hi
                }
        }
    }

    // epilogue straight from fragments: thread holds (m, n), (m+8, n) pairs
    #pragma unroll
    for (int mt = 0; mt < 4; mt++)
        #pragma unroll
        for (int nt = 0; nt < NTN8; nt++) {
            int m = m_base + mt * 16 + (lane >> 2);
            int n = n_base + nt * 8 + (lane & 3) * 2;
            epi(m,     n, make_float2(acc[mt][nt][0], acc[mt][nt][1]));
            epi(m + 8, n, make_float2(acc[mt][nt][2], acc[mt][nt][3]));
        }
}

// ---------------------------------------------------------------------------
// Epilogue functors (float2 at even n)
// ---------------------------------------------------------------------------
struct EpiQKV {
    int m0, n0; const float* bias;
    __device__ __forceinline__ void operator()(int mi, int ni, float2 v) const {
        int m = m0 + mi, n = n0 + ni;
        float2 bb = *(const float2*)(bias + n);
        v.x += bb.x; v.y += bb.y;
        int l = m >> 2, b = m & 3;
        int sec = n >> 10, e = n & 1023, h = e >> 6, d = e & 63;
        if (sec == 0) {
            v.x *= 0.125f; v.y *= 0.125f;
            *(float2*)(g_q + (((b * NH + h) * Lq + l) * Dh + d)) = v;
        } else if (sec == 1) {
            *(float2*)(g_k + (((b * NH + h) * Lq + l) * Dh + d)) = v;
        } else {
            // transposed (BH, D, L)
            size_t idx = ((size_t)(b * NH + h) * Dh + d) * Lq + l;
            g_v[idx]      = v.x;
            g_v[idx + Lq] = v.y;
        }
    }
};
struct EpiStore {
    float* C; int m0, n0;
    __device__ __forceinline__ void operator()(int mi, int ni, float2 v) const {
        *(float2*)(C + (size_t)(m0 + mi) * Lq + (n0 + ni)) = v;
    }
};
struct EpiCtx {
    int m0, b, h;
    __device__ __forceinline__ void operator()(int mi, int ni, float2 v) const {
        *(float2*)(g_ctx + (size_t)(m0 + mi) * (Bq * Eq) + b * Eq + h * Dh + ni) = v;
    }
};
struct EpiBias {
    float* C; const float* bias; int m0, n0;
    __device__ __forceinline__ void operator()(int mi, int ni, float2 v) const {
        float2 bb = *(const float2*)(bias + n0 + ni);
        v.x += bb.x; v.y += bb.y;
        *(float2*)(C + (size_t)(m0 + mi) * Eq + (n0 + ni)) = v;
    }
};

// ---------------------------------------------------------------------------
// Kernels
// ---------------------------------------------------------------------------
__global__ __launch_bounds__(256, 1) void k_qkv(const float* __restrict__ q,
                                                const float* __restrict__ W,
                                                const float* __restrict__ bias) {
    EpiQKV e{(int)blockIdx.y * 128, (int)blockIdx.x * 128, bias};
    mm_main<128>(q + (size_t)e.m0 * Eq, Eq, W + (size_t)e.n0 * Eq, Eq, Eq, e);
}

__global__ __launch_bounds__(256, 1) void k_scores(const float* __restrict__ er) {
    int z = blockIdx.z; int bh = z & 63; int use_er = z >> 6;
    int m0 = blockIdx.y * 128, n0 = blockIdx.x * 128;
    const float* A = g_q + (size_t)bh * Lq * Dh + (size_t)m0 * Dh;
    const float* B = use_er ? er + (size_t)n0 * Dh
                            : g_k + (size_t)bh * Lq * Dh + (size_t)n0 * Dh;
    EpiStore e{(use_er ? g_qe : g_s) + (size_t)bh * Lq * Lq, m0, n0};
    mm_main<128>(A, Dh, B, Dh, Dh, e);
}

__global__ __launch_bounds__(256) void k_softmax() {
    const int l  = blockIdx.x;
    const int bh = blockIdx.y;
    float* __restrict__ srow       = g_s  + ((size_t)bh * Lq + l) * Lq;
    const float* __restrict__ qrow = g_qe + ((size_t)bh * Lq + l) * Lq;
    const int tid = threadIdx.x;

    float vals[4];
    float mx = -3.4e38f;
    #pragma unroll
    for (int i = 0; i < 4; i++) {
        const int m = tid + i * 256;
        float v = srow[m];
        if (m <= l) v += qrow[m + (Lq - 1) - l];
        vals[i] = v;
        mx = fmaxf(mx, v);
    }
    __shared__ float red[256];
    red[tid] = mx; __syncthreads();
    for (int s = 128; s > 0; s >>= 1) {
        if (tid < s) red[tid] = fmaxf(red[tid], red[tid + s]);
        __syncthreads();
    }
    mx = red[0];
    __syncthreads();
    float sum = 0.f;
    #pragma unroll
    for (int i = 0; i < 4; i++) { vals[i] = __expf(vals[i] - mx); sum += vals[i]; }
    red[tid] = sum; __syncthreads();
    for (int s = 128; s > 0; s >>= 1) {
        if (tid < s) red[tid] += red[tid + s];
        __syncthreads();
    }
    const float inv = 1.0f / red[0];
    #pragma unroll
    for (int i = 0; i < 4; i++) srow[tid + i * 256] = vals[i] * inv;
}

__global__ __launch_bounds__(256, 1) void k_pv() {
    int bh = blockIdx.y, m0 = blockIdx.x * 128;
    EpiCtx e{m0, bh >> 4, bh & 15};
    mm_main<64>(g_s + (size_t)bh * Lq * Lq + (size_t)m0 * Lq, Lq,
                g_v + (size_t)bh * Dh * Lq, Lq, Lq, e);
}

__global__ __launch_bounds__(256, 1) void k_outproj(const float* __restrict__ W,
                                                    const float* __restrict__ bias,
                                                    float* __restrict__ out) {
    int m0 = blockIdx.y * 128, n0 = blockIdx.x * 128;
    EpiBias e{out, bias, m0, n0};
    mm_main<128>(g_ctx + (size_t)m0 * Eq, Eq, W + (size_t)n0 * Eq, Eq, Eq, e);
}

// ---------------------------------------------------------------------------
extern "C" void kernel_launch(void* const* d_in, const int* in_sizes, int n_in,
                              void* d_out, int out_size)
{
    (void)in_sizes; (void)n_in; (void)out_size;
    const float* query  = (const float*)d_in[0];
    const float* relpos = (const float*)d_in[1];
    const float* w_in   = (const float*)d_in[2];
    const float* b_in   = (const float*)d_in[3];
    const float* w_out  = (const float*)d_in[4];
    const float* b_out  = (const float*)d_in[5];
    float* out = (float*)d_out;

    k_qkv    <<<dim3(24, 32),    256>>>(query, w_in, b_in);
    k_scores <<<dim3(8, 8, 128), 256>>>(relpos);
    k_softmax<<<dim3(Lq, BH),    256>>>();
    k_pv     <<<dim3(8, BH),     256>>>();
    k_outproj<<<dim3(8, 32),     256>>>(w_out, b_out, out);
}

// round 4
// speedup vs baseline: 2.6526x; 1.0937x over previous
#include <cuda_runtime.h>
#include <cuda_bf16.h>
#include <stdint.h>

#define NH 16
#define Dh 64
#define Lq 1024
#define Bq 4
#define Eq 1024
#define BH 64

// ---- scratch (device globals) ----
__device__ float g_q[BH*Lq*Dh];          // (BH,L,D), q pre-scaled by 1/8
__device__ float g_k[BH*Lq*Dh];          // (BH,L,D)
__device__ float g_v[BH*Lq*Dh];          // (BH,D,L)  TRANSPOSED for PV
__device__ float g_qe[(size_t)BH*Lq*Lq]; // relpos logits (band tiles only)
__device__ float g_ctx[Lq*Bq*Eq];        // (L,B,E)

#define SWZ64(x)  ((x) ^ (((x) >> 3) & 0x30))
#define SWZ128(x) ((x) ^ (((x) >> 3) & 0x70))
#define SWZ256(x) ((x) ^ (((x) >> 4) & 0x70))

__device__ __forceinline__ void ldsm4(uint32_t (&r)[4], uint32_t addr) {
    asm volatile("ldmatrix.sync.aligned.m8n8.x4.shared.b16 {%0,%1,%2,%3}, [%4];"
                 : "=r"(r[0]), "=r"(r[1]), "=r"(r[2]), "=r"(r[3]) : "r"(addr));
}
__device__ __forceinline__ void mma_bf16(float (&d)[4], const uint32_t (&a)[4],
                                         uint32_t b0, uint32_t b1) {
    asm volatile("mma.sync.aligned.m16n8k16.row.col.f32.bf16.bf16.f32 "
                 "{%0,%1,%2,%3}, {%4,%5,%6,%7}, {%8,%9}, {%0,%1,%2,%3};"
                 : "+f"(d[0]), "+f"(d[1]), "+f"(d[2]), "+f"(d[3])
                 : "r"(a[0]), "r"(a[1]), "r"(a[2]), "r"(a[3]), "r"(b0), "r"(b1));
}
__device__ __forceinline__ void split_bf16(float4 v, uint2& hi, uint2& lo) {
    __nv_bfloat162 h0 = __floats2bfloat162_rn(v.x, v.y);
    __nv_bfloat162 h1 = __floats2bfloat162_rn(v.z, v.w);
    __nv_bfloat162 l0 = __floats2bfloat162_rn(v.x - __low2float(h0),  v.y - __high2float(h0));
    __nv_bfloat162 l1 = __floats2bfloat162_rn(v.z - __low2float(h1),  v.w - __high2float(h1));
    hi = make_uint2(*(uint32_t*)&h0, *(uint32_t*)&h1);
    lo = make_uint2(*(uint32_t*)&l0, *(uint32_t*)&l1);
}
__device__ __forceinline__ uint32_t packbf(float a, float b) {
    __nv_bfloat162 t = __floats2bfloat162_rn(a, b);
    return *(uint32_t*)&t;
}

// ---------------------------------------------------------------------------
// Generic GEMM (R3-verified): C(128 x NT) = A(128 x K) * B(NT x K)^T
// ---------------------------------------------------------------------------
template<int NT, class Epi>
__device__ __forceinline__ void mm_main(const float* __restrict__ A, int lda,
                                        const float* __restrict__ B, int ldb,
                                        int K, Epi epi)
{
    constexpr int WN   = NT / 4;
    constexpr int NTN8 = WN / 8;
    constexpr int NB16 = WN / 16;
    constexpr int BI   = NT / 32;

    __shared__ __align__(1024) char smb[16384 + 2 * NT * 64];
    const uint32_t su   = (uint32_t)__cvta_generic_to_shared(smb);
    const uint32_t suA  = su;
    const uint32_t suAl = su + 8192;
    const uint32_t suB  = su + 16384;
    const uint32_t suBl = su + 16384 + NT * 64;

    const int tid  = threadIdx.x;
    const int lane = tid & 31, w = tid >> 5;
    const int m_base = (w & 1) * 64;
    const int n_base = (w >> 1) * WN;

    float acc[4][NTN8][4];
    #pragma unroll
    for (int i = 0; i < 4; i++)
        #pragma unroll
        for (int j = 0; j < NTN8; j++)
            #pragma unroll
            for (int q = 0; q < 4; q++) acc[i][j][q] = 0.f;

    const uint32_t a_row = lane & 15;
    const uint32_t a_k8  = (lane >> 4) * 8;
    const uint32_t b_row = (lane & 7) + ((lane >> 4) & 1) * 8;
    const uint32_t b_k8  = ((lane >> 3) & 1) * 8;

    for (int kb = 0; kb < K; kb += 32) {
        float4 va[4], vb[BI];
        #pragma unroll
        for (int i = 0; i < 4; i++) {
            int qd = tid + i * 256;
            int r = qd >> 3, c = (qd & 7) * 4;
            va[i] = *(const float4*)(A + (size_t)r * lda + kb + c);
        }
        #pragma unroll
        for (int i = 0; i < BI; i++) {
            int qd = tid + i * 256;
            int r = qd >> 3, c = (qd & 7) * 4;
            vb[i] = *(const float4*)(B + (size_t)r * ldb + kb + c);
        }
        __syncthreads();
        #pragma unroll
        for (int i = 0; i < 4; i++) {
            int qd = tid + i * 256;
            int r = qd >> 3, c = (qd & 7) * 4;
            uint2 hi, lo; split_bf16(va[i], hi, lo);
            uint32_t off = SWZ64((uint32_t)(r * 64 + c * 2));
            *(uint2*)(smb + off)        = hi;
            *(uint2*)(smb + 8192 + off) = lo;
        }
        #pragma unroll
        for (int i = 0; i < BI; i++) {
            int qd = tid + i * 256;
            int r = qd >> 3, c = (qd & 7) * 4;
            uint2 hi, lo; split_bf16(vb[i], hi, lo);
            uint32_t off = SWZ64((uint32_t)(r * 64 + c * 2));
            *(uint2*)(smb + 16384 + off)           = hi;
            *(uint2*)(smb + 16384 + NT * 64 + off) = lo;
        }
        __syncthreads();

        #pragma unroll
        for (int kc = 0; kc < 2; kc++) {
            uint32_t ah[4][4], al[4][4];
            #pragma unroll
            for (int mt = 0; mt < 4; mt++) {
                uint32_t off = (uint32_t)((m_base + mt * 16 + a_row) * 64
                                          + (kc * 16 + a_k8) * 2);
                ldsm4(ah[mt], suA  + SWZ64(off));
                ldsm4(al[mt], suAl + SWZ64(off));
            }
            uint32_t bh[NB16][4], bl[NB16][4];
            #pragma unroll
            for (int nb = 0; nb < NB16; nb++) {
                uint32_t off = (uint32_t)((n_base + nb * 16 + b_row) * 64
                                          + (kc * 16 + b_k8) * 2);
                ldsm4(bh[nb], suB  + SWZ64(off));
                ldsm4(bl[nb], suBl + SWZ64(off));
            }
            #pragma unroll
            for (int mt = 0; mt < 4; mt++)
                #pragma unroll
                for (int nt = 0; nt < NTN8; nt++) {
                    uint32_t b0h = bh[nt >> 1][(nt & 1) * 2];
                    uint32_t b1h = bh[nt >> 1][(nt & 1) * 2 + 1];
                    uint32_t b0l = bl[nt >> 1][(nt & 1) * 2];
                    uint32_t b1l = bl[nt >> 1][(nt & 1) * 2 + 1];
                    mma_bf16(acc[mt][nt], ah[mt], b0h, b1h);
                    mma_bf16(acc[mt][nt], ah[mt], b0l, b1l);
                    mma_bf16(acc[mt][nt], al[mt], b0h, b1h);
                }
        }
    }

    #pragma unroll
    for (int mt = 0; mt < 4; mt++)
        #pragma unroll
        for (int nt = 0; nt < NTN8; nt++) {
            int m = m_base + mt * 16 + (lane >> 2);
            int n = n_base + nt * 8 + (lane & 3) * 2;
            epi(m,     n, make_float2(acc[mt][nt][0], acc[mt][nt][1]));
            epi(m + 8, n, make_float2(acc[mt][nt][2], acc[mt][nt][3]));
        }
}

// ---------------------------------------------------------------------------
// Epilogues
// ---------------------------------------------------------------------------
struct EpiQKV {
    int m0, n0; const float* bias;
    __device__ __forceinline__ void operator()(int mi, int ni, float2 v) const {
        int m = m0 + mi, n = n0 + ni;
        float2 bb = *(const float2*)(bias + n);
        v.x += bb.x; v.y += bb.y;
        int l = m >> 2, b = m & 3;
        int sec = n >> 10, e = n & 1023, h = e >> 6, d = e & 63;
        if (sec == 0) {
            v.x *= 0.125f; v.y *= 0.125f;
            *(float2*)(g_q + (((b * NH + h) * Lq + l) * Dh + d)) = v;
        } else if (sec == 1) {
            *(float2*)(g_k + (((b * NH + h) * Lq + l) * Dh + d)) = v;
        } else {
            size_t idx = ((size_t)(b * NH + h) * Dh + d) * Lq + l;
            g_v[idx]      = v.x;
            g_v[idx + Lq] = v.y;
        }
    }
};
struct EpiStore {
    float* C; int m0, n0;
    __device__ __forceinline__ void operator()(int mi, int ni, float2 v) const {
        *(float2*)(C + (size_t)(m0 + mi) * Lq + (n0 + ni)) = v;
    }
};
struct EpiBias {
    float* C; const float* bias; int m0, n0;
    __device__ __forceinline__ void operator()(int mi, int ni, float2 v) const {
        float2 bb = *(const float2*)(bias + n0 + ni);
        v.x += bb.x; v.y += bb.y;
        *(float2*)(C + (size_t)(m0 + mi) * Eq + (n0 + ni)) = v;
    }
};

// ---------------------------------------------------------------------------
__global__ __launch_bounds__(256, 1) void k_qkv(const float* __restrict__ q,
                                                const float* __restrict__ W,
                                                const float* __restrict__ bias) {
    EpiQKV e{(int)blockIdx.y * 128, (int)blockIdx.x * 128, bias};
    mm_main<128>(q + (size_t)e.m0 * Eq, Eq, W + (size_t)e.n0 * Eq, Eq, Eq, e);
}

// QE = Q * ER^T ; only band tiles (mi+ni >= 7) are ever read downstream
__global__ __launch_bounds__(256, 1) void k_qe(const float* __restrict__ er) {
    if (blockIdx.x + blockIdx.y < 7) return;
    int bh = blockIdx.z;
    int m0 = blockIdx.y * 128, n0 = blockIdx.x * 128;
    EpiStore e{g_qe + (size_t)bh * Lq * Lq, m0, n0};
    mm_main<128>(g_q + (size_t)bh * Lq * Dh + (size_t)m0 * Dh, Dh,
                 er + (size_t)n0 * Dh, Dh, Dh, e);
}

// ---------------------------------------------------------------------------
// Fused attention: S=QK^T (+srel from g_qe) -> online softmax -> O=PV
// grid (8 m-tiles, 64 bh), 256 thr (8 warps x 16 rows). dyn smem 64KB.
// ---------------------------------------------------------------------------
__global__ __launch_bounds__(256, 1) void k_attn() {
    extern __shared__ char sm[];
    char* pKh = sm;          char* pKl = sm + 16384;
    char* pVh = sm + 32768;  char* pVl = sm + 49152;
    const uint32_t suKh = (uint32_t)__cvta_generic_to_shared(sm);
    const uint32_t suKl = suKh + 16384;
    const uint32_t suVh = suKh + 32768;
    const uint32_t suVl = suKh + 49152;

    const int tid = threadIdx.x, lane = tid & 31, w = tid >> 5;
    const int m0 = blockIdx.x * 128, bh = blockIdx.y;
    const int rb = w * 16;

    const float* __restrict__ Qg = g_q + (size_t)bh * Lq * Dh + (size_t)m0 * Dh;
    const float* __restrict__ Kg = g_k + (size_t)bh * Lq * Dh;
    const float* __restrict__ Vg = g_v + (size_t)bh * Dh * Lq;   // (D, L)

    // ---- stage Q (128x64) through K buffers, pull A-frags to registers ----
    #pragma unroll
    for (int i = 0; i < 8; i++) {
        int qd = tid + i * 256; int r = qd >> 4, c = (qd & 15) * 4;
        float4 v = *(const float4*)(Qg + (size_t)r * Dh + c);
        uint2 hi, lo; split_bf16(v, hi, lo);
        uint32_t off = SWZ128((uint32_t)(r * 128 + c * 2));
        *(uint2*)(pKh + off) = hi; *(uint2*)(pKl + off) = lo;
    }
    __syncthreads();
    uint32_t qh[4][4], ql[4][4];
    {
        uint32_t arow = rb + (lane & 15);
        uint32_t ak   = (lane >> 4) * 8;
        #pragma unroll
        for (int kc = 0; kc < 4; kc++) {
            uint32_t off = SWZ128(arow * 128 + (kc * 16 + ak) * 2);
            ldsm4(qh[kc], suKh + off);
            ldsm4(ql[kc], suKl + off);
        }
    }

    float o[8][4];
    #pragma unroll
    for (int f = 0; f < 8; f++) { o[f][0]=0.f; o[f][1]=0.f; o[f][2]=0.f; o[f][3]=0.f; }
    float mst0 = -3.4e38f, mst1 = -3.4e38f, sum0 = 0.f, sum1 = 0.f;

    const uint32_t brow = (lane & 7) + ((lane >> 4) & 1) * 8;
    const uint32_t bk8  = ((lane >> 3) & 1) * 8;
    const int l0 = m0 + rb + (lane >> 2), l1 = l0 + 8;
    const float L2E = 1.4426950408889634f;

    for (int nb = 0; nb < 8; nb++) {
        const int n0 = nb * 128;
        __syncthreads();
        #pragma unroll
        for (int i = 0; i < 8; i++) {        // K block 128x64
            int qd = tid + i * 256; int r = qd >> 4, c = (qd & 15) * 4;
            float4 v = *(const float4*)(Kg + (size_t)(n0 + r) * Dh + c);
            uint2 hi, lo; split_bf16(v, hi, lo);
            uint32_t off = SWZ128((uint32_t)(r * 128 + c * 2));
            *(uint2*)(pKh + off) = hi; *(uint2*)(pKl + off) = lo;
        }
        #pragma unroll
        for (int i = 0; i < 8; i++) {        // V^T block 64x128
            int qd = tid + i * 256; int r = qd >> 5, c = (qd & 31) * 4;
            float4 v = *(const float4*)(Vg + (size_t)r * Lq + n0 + c);
            uint2 hi, lo; split_bf16(v, hi, lo);
            uint32_t off = SWZ256((uint32_t)(r * 256 + c * 2));
            *(uint2*)(pVh + off) = hi; *(uint2*)(pVl + off) = lo;
        }
        __syncthreads();

        // S = Q K^T (split x3)
        float s[16][4];
        #pragma unroll
        for (int f = 0; f < 16; f++) { s[f][0]=0.f; s[f][1]=0.f; s[f][2]=0.f; s[f][3]=0.f; }
        #pragma unroll
        for (int n16 = 0; n16 < 8; n16++) {
            #pragma unroll
            for (int kc = 0; kc < 4; kc++) {
                uint32_t off = SWZ128((n16 * 16 + brow) * 128 + (kc * 16 + bk8) * 2);
                uint32_t kh4[4], kl4[4];
                ldsm4(kh4, suKh + off); ldsm4(kl4, suKl + off);
                mma_bf16(s[2*n16],   qh[kc], kh4[0], kh4[1]);
                mma_bf16(s[2*n16],   qh[kc], kl4[0], kl4[1]);
                mma_bf16(s[2*n16],   ql[kc], kh4[0], kh4[1]);
                mma_bf16(s[2*n16+1], qh[kc], kh4[2], kh4[3]);
                mma_bf16(s[2*n16+1], qh[kc], kl4[2], kl4[3]);
                mma_bf16(s[2*n16+1], ql[kc], kh4[2], kh4[3]);
            }
        }

        // srel: s[l][m] += qe[l][1023 + m - l]  for m <= l
        if (n0 <= m0) {
            const float* q0 = g_qe + ((size_t)bh * Lq + l0) * Lq + (1023 - l0);
            const float* q1 = g_qe + ((size_t)bh * Lq + l1) * Lq + (1023 - l1);
            #pragma unroll
            for (int f = 0; f < 16; f++) {
                int m = n0 + f * 8 + (lane & 3) * 2;
                if (m < l0)       { s[f][0] += q0[m]; s[f][1] += q0[m + 1]; }
                else if (m == l0) { s[f][0] += q0[m]; }
                if (m < l1)       { s[f][2] += q1[m]; s[f][3] += q1[m + 1]; }
                else if (m == l1) { s[f][2] += q1[m]; }
            }
        }

        // online softmax (rows are quad-local: lanes L, L^1, L^2 share rows)
        float mx0 = -3.4e38f, mx1 = -3.4e38f;
        #pragma unroll
        for (int f = 0; f < 16; f++) {
            mx0 = fmaxf(mx0, fmaxf(s[f][0], s[f][1]));
            mx1 = fmaxf(mx1, fmaxf(s[f][2], s[f][3]));
        }
        mx0 = fmaxf(mx0, __shfl_xor_sync(0xffffffffu, mx0, 1));
        mx0 = fmaxf(mx0, __shfl_xor_sync(0xffffffffu, mx0, 2));
        mx1 = fmaxf(mx1, __shfl_xor_sync(0xffffffffu, mx1, 1));
        mx1 = fmaxf(mx1, __shfl_xor_sync(0xffffffffu, mx1, 2));
        float nm0 = fmaxf(mst0, mx0), nm1 = fmaxf(mst1, mx1);
        float sc0 = exp2f((mst0 - nm0) * L2E), sc1 = exp2f((mst1 - nm1) * L2E);
        mst0 = nm0; mst1 = nm1;
        sum0 *= sc0; sum1 *= sc1;
        #pragma unroll
        for (int f = 0; f < 8; f++) {
            o[f][0] *= sc0; o[f][1] *= sc0; o[f][2] *= sc1; o[f][3] *= sc1;
        }
        #pragma unroll
        for (int f = 0; f < 16; f++) {
            s[f][0] = exp2f((s[f][0] - nm0) * L2E);
            s[f][1] = exp2f((s[f][1] - nm0) * L2E);
            s[f][2] = exp2f((s[f][2] - nm1) * L2E);
            s[f][3] = exp2f((s[f][3] - nm1) * L2E);
            sum0 += s[f][0] + s[f][1];
            sum1 += s[f][2] + s[f][3];
        }

        // O += P V  (P re-packed from S frags, split x3)
        #pragma unroll
        for (int kk = 0; kk < 8; kk++) {
            uint32_t ah[4], al[4];
            {
                float p00 = s[2*kk][0],   p01 = s[2*kk][1];
                float p10 = s[2*kk][2],   p11 = s[2*kk][3];
                float p20 = s[2*kk+1][0], p21 = s[2*kk+1][1];
                float p30 = s[2*kk+1][2], p31 = s[2*kk+1][3];
                ah[0] = packbf(p00, p01); ah[1] = packbf(p10, p11);
                ah[2] = packbf(p20, p21); ah[3] = packbf(p30, p31);
                __nv_bfloat162 h;
                h = *(__nv_bfloat162*)&ah[0];
                al[0] = packbf(p00 - __low2float(h), p01 - __high2float(h));
                h = *(__nv_bfloat162*)&ah[1];
                al[1] = packbf(p10 - __low2float(h), p11 - __high2float(h));
                h = *(__nv_bfloat162*)&ah[2];
                al[2] = packbf(p20 - __low2float(h), p21 - __high2float(h));
                h = *(__nv_bfloat162*)&ah[3];
                al[3] = packbf(p30 - __low2float(h), p31 - __high2float(h));
            }
            #pragma unroll
            for (int n16 = 0; n16 < 4; n16++) {
                uint32_t off = SWZ256((n16 * 16 + brow) * 256 + (kk * 16 + bk8) * 2);
                uint32_t vh4[4], vl4[4];
                ldsm4(vh4, suVh + off); ldsm4(vl4, suVl + off);
                mma_bf16(o[2*n16],   ah, vh4[0], vh4[1]);
                mma_bf16(o[2*n16],   ah, vl4[0], vl4[1]);
                mma_bf16(o[2*n16],   al, vh4[0], vh4[1]);
                mma_bf16(o[2*n16+1], ah, vh4[2], vh4[3]);
                mma_bf16(o[2*n16+1], ah, vl4[2], vl4[3]);
                mma_bf16(o[2*n16+1], al, vh4[2], vh4[3]);
            }
        }
    }

    // finalize: divide by row sums, write ctx (L,B,E)
    sum0 += __shfl_xor_sync(0xffffffffu, sum0, 1);
    sum0 += __shfl_xor_sync(0xffffffffu, sum0, 2);
    sum1 += __shfl_xor_sync(0xffffffffu, sum1, 1);
    sum1 += __shfl_xor_sync(0xffffffffu, sum1, 2);
    const float inv0 = 1.0f / sum0, inv1 = 1.0f / sum1;
    const int b = bh >> 4, h = bh & 15;
    #pragma unroll
    for (int f = 0; f < 8; f++) {
        int d = f * 8 + (lane & 3) * 2;
        float2 v0 = make_float2(o[f][0] * inv0, o[f][1] * inv0);
        float2 v1 = make_float2(o[f][2] * inv1, o[f][3] * inv1);
        *(float2*)(g_ctx + (size_t)l0 * (Bq * Eq) + b * Eq + h * Dh + d) = v0;
        *(float2*)(g_ctx + (size_t)l1 * (Bq * Eq) + b * Eq + h * Dh + d) = v1;
    }
}

__global__ __launch_bounds__(256, 1) void k_outproj(const float* __restrict__ W,
                                                    const float* __restrict__ bias,
                                                    float* __restrict__ out) {
    int m0 = blockIdx.y * 128, n0 = blockIdx.x * 128;
    EpiBias e{out, bias, m0, n0};
    mm_main<128>(g_ctx + (size_t)m0 * Eq, Eq, W + (size_t)n0 * Eq, Eq, Eq, e);
}

// ---------------------------------------------------------------------------
extern "C" void kernel_launch(void* const* d_in, const int* in_sizes, int n_in,
                              void* d_out, int out_size)
{
    (void)in_sizes; (void)n_in; (void)out_size;
    const float* query  = (const float*)d_in[0];
    const float* relpos = (const float*)d_in[1];
    const float* w_in   = (const float*)d_in[2];
    const float* b_in   = (const float*)d_in[3];
    const float* w_out  = (const float*)d_in[4];
    const float* b_out  = (const float*)d_in[5];
    float* out = (float*)d_out;

    cudaFuncSetAttribute(k_attn, cudaFuncAttributeMaxDynamicSharedMemorySize, 65536);

    k_qkv    <<<dim3(24, 32),   256>>>(query, w_in, b_in);
    k_qe     <<<dim3(8, 8, 64), 256>>>(relpos);
    k_attn   <<<dim3(8, 64),    256, 65536>>>();
    k_outproj<<<dim3(8, 32),    256>>>(w_out, b_out, out);
}

// round 5
// speedup vs baseline: 2.8885x; 1.0889x over previous
#include <cuda_runtime.h>
#include <cuda_bf16.h>
#include <stdint.h>

#define NH 16
#define Dh 64
#define Lq 1024
#define Bq 4
#define Eq 1024
#define BH 64

// ---- scratch (device globals) ----
__device__ float g_q[BH*Lq*Dh];          // (BH,L,D), q pre-scaled by 1/8
__device__ float g_k[BH*Lq*Dh];          // (BH,L,D)
__device__ float g_v[BH*Lq*Dh];          // (BH,D,L)  TRANSPOSED for PV
__device__ float g_qe[(size_t)BH*Lq*Lq]; // relpos logits (band tiles only)
__device__ float g_ctx[Lq*Bq*Eq];        // (L,B,E)

#define SWZ64(x)  ((x) ^ (((x) >> 3) & 0x30))
#define SWZ128(x) ((x) ^ (((x) >> 3) & 0x70))
#define SWZ256(x) ((x) ^ (((x) >> 4) & 0x70))

__device__ __forceinline__ void ldsm4(uint32_t (&r)[4], uint32_t addr) {
    asm volatile("ldmatrix.sync.aligned.m8n8.x4.shared.b16 {%0,%1,%2,%3}, [%4];"
                 : "=r"(r[0]), "=r"(r[1]), "=r"(r[2]), "=r"(r[3]) : "r"(addr));
}
__device__ __forceinline__ void mma_bf16(float (&d)[4], const uint32_t (&a)[4],
                                         uint32_t b0, uint32_t b1) {
    asm volatile("mma.sync.aligned.m16n8k16.row.col.f32.bf16.bf16.f32 "
                 "{%0,%1,%2,%3}, {%4,%5,%6,%7}, {%8,%9}, {%0,%1,%2,%3};"
                 : "+f"(d[0]), "+f"(d[1]), "+f"(d[2]), "+f"(d[3])
                 : "r"(a[0]), "r"(a[1]), "r"(a[2]), "r"(a[3]), "r"(b0), "r"(b1));
}
__device__ __forceinline__ void split_bf16(float4 v, uint2& hi, uint2& lo) {
    __nv_bfloat162 h0 = __floats2bfloat162_rn(v.x, v.y);
    __nv_bfloat162 h1 = __floats2bfloat162_rn(v.z, v.w);
    __nv_bfloat162 l0 = __floats2bfloat162_rn(v.x - __low2float(h0),  v.y - __high2float(h0));
    __nv_bfloat162 l1 = __floats2bfloat162_rn(v.z - __low2float(h1),  v.w - __high2float(h1));
    hi = make_uint2(*(uint32_t*)&h0, *(uint32_t*)&h1);
    lo = make_uint2(*(uint32_t*)&l0, *(uint32_t*)&l1);
}
__device__ __forceinline__ uint32_t packbf(float a, float b) {
    __nv_bfloat162 t = __floats2bfloat162_rn(a, b);
    return *(uint32_t*)&t;
}

// ---------------------------------------------------------------------------
// Double-buffered GEMM: C(128 x NT) = A(128 x K) * B(NT x K)^T
// 256 thr, warp grid 2x4. Dynamic smem: 2 stages of (A 16KB + B NT*128 B).
// One __syncthreads per 32-K iteration; LDG for next stage in flight over MMA.
// ---------------------------------------------------------------------------
template<int NT, class Epi>
__device__ __forceinline__ void mm_main(const float* __restrict__ A, int lda,
                                        const float* __restrict__ B, int ldb,
                                        int K, Epi epi)
{
    constexpr int WN   = NT / 4;
    constexpr int NTN8 = WN / 8;
    constexpr int NB16 = WN / 16;
    constexpr int BI   = NT / 32;
    constexpr int ASZ  = 8192;         // 128 x 32 bf16
    constexpr int BSZ  = NT * 64;      // NT x 32 bf16
    constexpr int STG  = 2 * ASZ + 2 * BSZ;

    extern __shared__ char dsm[];
    const uint32_t su = (uint32_t)__cvta_generic_to_shared(dsm);

    const int tid  = threadIdx.x;
    const int lane = tid & 31, w = tid >> 5;
    const int m_base = (w & 1) * 64;
    const int n_base = (w >> 1) * WN;

    float acc[4][NTN8][4];
    #pragma unroll
    for (int i = 0; i < 4; i++)
        #pragma unroll
        for (int j = 0; j < NTN8; j++)
            #pragma unroll
            for (int q = 0; q < 4; q++) acc[i][j][q] = 0.f;

    const uint32_t a_row = lane & 15;
    const uint32_t a_k8  = (lane >> 4) * 8;
    const uint32_t b_row = (lane & 7) + ((lane >> 4) & 1) * 8;
    const uint32_t b_k8  = ((lane >> 3) & 1) * 8;

    float4 va[4], vb[BI];

    auto gload = [&](int kb) {
        #pragma unroll
        for (int i = 0; i < 4; i++) {
            int qd = tid + i * 256; int r = qd >> 3, c = (qd & 7) * 4;
            va[i] = *(const float4*)(A + (size_t)r * lda + kb + c);
        }
        #pragma unroll
        for (int i = 0; i < BI; i++) {
            int qd = tid + i * 256; int r = qd >> 3, c = (qd & 7) * 4;
            vb[i] = *(const float4*)(B + (size_t)r * ldb + kb + c);
        }
    };
    auto sstore = [&](int s) {
        char* base = dsm + s * STG;
        #pragma unroll
        for (int i = 0; i < 4; i++) {
            int qd = tid + i * 256; int r = qd >> 3, c = (qd & 7) * 4;
            uint2 hi, lo; split_bf16(va[i], hi, lo);
            uint32_t off = SWZ64((uint32_t)(r * 64 + c * 2));
            *(uint2*)(base + off)       = hi;
            *(uint2*)(base + ASZ + off) = lo;
        }
        #pragma unroll
        for (int i = 0; i < BI; i++) {
            int qd = tid + i * 256; int r = qd >> 3, c = (qd & 7) * 4;
            uint2 hi, lo; split_bf16(vb[i], hi, lo);
            uint32_t off = SWZ64((uint32_t)(r * 64 + c * 2));
            *(uint2*)(base + 2 * ASZ + off)       = hi;
            *(uint2*)(base + 2 * ASZ + BSZ + off) = lo;
        }
    };
    auto domma = [&](int s) {
        const uint32_t sbA  = su + s * STG;
        const uint32_t sbAl = sbA + ASZ;
        const uint32_t sbB  = sbA + 2 * ASZ;
        const uint32_t sbBl = sbB + BSZ;
        #pragma unroll
        for (int kc = 0; kc < 2; kc++) {
            uint32_t ah[4][4], al[4][4];
            #pragma unroll
            for (int mt = 0; mt < 4; mt++) {
                uint32_t off = SWZ64((uint32_t)((m_base + mt * 16 + a_row) * 64
                                                + (kc * 16 + a_k8) * 2));
                ldsm4(ah[mt], sbA  + off);
                ldsm4(al[mt], sbAl + off);
            }
            uint32_t bh[NB16][4], bl[NB16][4];
            #pragma unroll
            for (int nb = 0; nb < NB16; nb++) {
                uint32_t off = SWZ64((uint32_t)((n_base + nb * 16 + b_row) * 64
                                                + (kc * 16 + b_k8) * 2));
                ldsm4(bh[nb], sbB  + off);
                ldsm4(bl[nb], sbBl + off);
            }
            #pragma unroll
            for (int mt = 0; mt < 4; mt++)
                #pragma unroll
                for (int nt = 0; nt < NTN8; nt++) {
                    uint32_t b0h = bh[nt >> 1][(nt & 1) * 2];
                    uint32_t b1h = bh[nt >> 1][(nt & 1) * 2 + 1];
                    uint32_t b0l = bl[nt >> 1][(nt & 1) * 2];
                    uint32_t b1l = bl[nt >> 1][(nt & 1) * 2 + 1];
                    mma_bf16(acc[mt][nt], ah[mt], b0h, b1h);
                    mma_bf16(acc[mt][nt], ah[mt], b0l, b1l);
                    mma_bf16(acc[mt][nt], al[mt], b0h, b1h);
                }
        }
    };

    gload(0); sstore(0); __syncthreads();
    const int nk = K >> 5;
    for (int i = 0; i < nk; i++) {
        if (i + 1 < nk) gload((i + 1) << 5);   // LDGs in flight over MMA
        domma(i & 1);
        if (i + 1 < nk) sstore((i + 1) & 1);
        __syncthreads();
    }

    #pragma unroll
    for (int mt = 0; mt < 4; mt++)
        #pragma unroll
        for (int nt = 0; nt < NTN8; nt++) {
            int m = m_base + mt * 16 + (lane >> 2);
            int n = n_base + nt * 8 + (lane & 3) * 2;
            epi(m,     n, make_float2(acc[mt][nt][0], acc[mt][nt][1]));
            epi(m + 8, n, make_float2(acc[mt][nt][2], acc[mt][nt][3]));
        }
}

// ---------------------------------------------------------------------------
// Epilogues
// ---------------------------------------------------------------------------
struct EpiQKV {
    int m0, n0; const float* bias;
    __device__ __forceinline__ void operator()(int mi, int ni, float2 v) const {
        int m = m0 + mi, n = n0 + ni;
        float2 bb = *(const float2*)(bias + n);
        v.x += bb.x; v.y += bb.y;
        int l = m >> 2, b = m & 3;
        int sec = n >> 10, e = n & 1023, h = e >> 6, d = e & 63;
        if (sec == 0) {
            v.x *= 0.125f; v.y *= 0.125f;
            *(float2*)(g_q + (((b * NH + h) * Lq + l) * Dh + d)) = v;
        } else if (sec == 1) {
            *(float2*)(g_k + (((b * NH + h) * Lq + l) * Dh + d)) = v;
        } else {
            size_t idx = ((size_t)(b * NH + h) * Dh + d) * Lq + l;
            g_v[idx]      = v.x;
            g_v[idx + Lq] = v.y;
        }
    }
};
struct EpiStore {
    float* C; int m0, n0;
    __device__ __forceinline__ void operator()(int mi, int ni, float2 v) const {
        *(float2*)(C + (size_t)(m0 + mi) * Lq + (n0 + ni)) = v;
    }
};
struct EpiBias {
    float* C; const float* bias; int m0, n0;
    __device__ __forceinline__ void operator()(int mi, int ni, float2 v) const {
        float2 bb = *(const float2*)(bias + n0 + ni);
        v.x += bb.x; v.y += bb.y;
        *(float2*)(C + (size_t)(m0 + mi) * Eq + (n0 + ni)) = v;
    }
};

// ---------------------------------------------------------------------------
__global__ __launch_bounds__(256, 1) void k_qkv(const float* __restrict__ q,
                                                const float* __restrict__ W,
                                                const float* __restrict__ bias) {
    EpiQKV e{(int)blockIdx.y * 128, (int)blockIdx.x * 128, bias};
    mm_main<128>(q + (size_t)e.m0 * Eq, Eq, W + (size_t)e.n0 * Eq, Eq, Eq, e);
}

__global__ __launch_bounds__(256, 1) void k_qe(const float* __restrict__ er) {
    if (blockIdx.x + blockIdx.y < 7) return;   // band tiles only
    int bh = blockIdx.z;
    int m0 = blockIdx.y * 128, n0 = blockIdx.x * 128;
    EpiStore e{g_qe + (size_t)bh * Lq * Lq, m0, n0};
    mm_main<128>(g_q + (size_t)bh * Lq * Dh + (size_t)m0 * Dh, Dh,
                 er + (size_t)n0 * Dh, Dh, Dh, e);
}

// ---------------------------------------------------------------------------
// Fused attention, double-buffered K/V stages (2 x 64KB dynamic smem)
// ---------------------------------------------------------------------------
__global__ __launch_bounds__(256, 1) void k_attn() {
    extern __shared__ char sm[];
    const uint32_t su = (uint32_t)__cvta_generic_to_shared(sm);
    // stage s: Kh = s*65536, Kl = +16384, Vh = +32768, Vl = +49152

    const int tid = threadIdx.x, lane = tid & 31, w = tid >> 5;
    const int m0 = blockIdx.x * 128, bh = blockIdx.y;
    const int rb = w * 16;

    const float* __restrict__ Qg = g_q + (size_t)bh * Lq * Dh + (size_t)m0 * Dh;
    const float* __restrict__ Kg = g_k + (size_t)bh * Lq * Dh;
    const float* __restrict__ Vg = g_v + (size_t)bh * Dh * Lq;   // (D, L)

    // ---- stage Q through stage0 K area, pull A-frags to registers ----
    #pragma unroll
    for (int i = 0; i < 8; i++) {
        int qd = tid + i * 256; int r = qd >> 4, c = (qd & 15) * 4;
        float4 v = *(const float4*)(Qg + (size_t)r * Dh + c);
        uint2 hi, lo; split_bf16(v, hi, lo);
        uint32_t off = SWZ128((uint32_t)(r * 128 + c * 2));
        *(uint2*)(sm + off)         = hi;
        *(uint2*)(sm + 16384 + off) = lo;
    }
    __syncthreads();
    uint32_t qh[4][4], ql[4][4];
    {
        uint32_t arow = rb + (lane & 15);
        uint32_t ak   = (lane >> 4) * 8;
        #pragma unroll
        for (int kc = 0; kc < 4; kc++) {
            uint32_t off = SWZ128(arow * 128 + (kc * 16 + ak) * 2);
            ldsm4(qh[kc], su + off);
            ldsm4(ql[kc], su + 16384 + off);
        }
    }
    __syncthreads();   // all warps done reading Q before stage0 is refilled

    float4 ka[8], vv[8];
    auto loadK = [&](int n0) {
        #pragma unroll
        for (int i = 0; i < 8; i++) {
            int qd = tid + i * 256; int r = qd >> 4, c = (qd & 15) * 4;
            ka[i] = *(const float4*)(Kg + (size_t)(n0 + r) * Dh + c);
        }
    };
    auto storeK = [&](int s) {
        char* base = sm + s * 65536;
        #pragma unroll
        for (int i = 0; i < 8; i++) {
            int qd = tid + i * 256; int r = qd >> 4, c = (qd & 15) * 4;
            uint2 hi, lo; split_bf16(ka[i], hi, lo);
            uint32_t off = SWZ128((uint32_t)(r * 128 + c * 2));
            *(uint2*)(base + off)         = hi;
            *(uint2*)(base + 16384 + off) = lo;
        }
    };
    auto loadV = [&](int n0) {
        #pragma unroll
        for (int i = 0; i < 8; i++) {
            int qd = tid + i * 256; int r = qd >> 5, c = (qd & 31) * 4;
            vv[i] = *(const float4*)(Vg + (size_t)r * Lq + n0 + c);
        }
    };
    auto storeV = [&](int s) {
        char* base = sm + s * 65536 + 32768;
        #pragma unroll
        for (int i = 0; i < 8; i++) {
            int qd = tid + i * 256; int r = qd >> 5, c = (qd & 31) * 4;
            uint2 hi, lo; split_bf16(vv[i], hi, lo);
            uint32_t off = SWZ256((uint32_t)(r * 256 + c * 2));
            *(uint2*)(base + off)         = hi;
            *(uint2*)(base + 16384 + off) = lo;
        }
    };

    float o[8][4];
    #pragma unroll
    for (int f = 0; f < 8; f++) { o[f][0]=0.f; o[f][1]=0.f; o[f][2]=0.f; o[f][3]=0.f; }
    float mst0 = -3.4e38f, mst1 = -3.4e38f, sum0 = 0.f, sum1 = 0.f;

    const uint32_t brow = (lane & 7) + ((lane >> 4) & 1) * 8;
    const uint32_t bk8  = ((lane >> 3) & 1) * 8;
    const int l0 = m0 + rb + (lane >> 2), l1 = l0 + 8;
    const float L2E = 1.4426950408889634f;

    // preload stage 0
    loadK(0); storeK(0);
    loadV(0); storeV(0);
    __syncthreads();

    for (int nb = 0; nb < 8; nb++) {
        const int n0  = nb * 128;
        const int cur = nb & 1;
        const uint32_t suK  = su + cur * 65536;
        const uint32_t suKl = suK + 16384;
        const uint32_t suV  = suK + 32768;
        const uint32_t suVl = suK + 49152;

        if (nb < 7) loadK(n0 + 128);       // LDGs in flight over S-MMA

        // S = Q K^T (split x3)
        float s[16][4];
        #pragma unroll
        for (int f = 0; f < 16; f++) { s[f][0]=0.f; s[f][1]=0.f; s[f][2]=0.f; s[f][3]=0.f; }
        #pragma unroll
        for (int n16 = 0; n16 < 8; n16++) {
            #pragma unroll
            for (int kc = 0; kc < 4; kc++) {
                uint32_t off = SWZ128((n16 * 16 + brow) * 128 + (kc * 16 + bk8) * 2);
                uint32_t kh4[4], kl4[4];
                ldsm4(kh4, suK + off); ldsm4(kl4, suKl + off);
                mma_bf16(s[2*n16],   qh[kc], kh4[0], kh4[1]);
                mma_bf16(s[2*n16],   qh[kc], kl4[0], kl4[1]);
                mma_bf16(s[2*n16],   ql[kc], kh4[0], kh4[1]);
                mma_bf16(s[2*n16+1], qh[kc], kh4[2], kh4[3]);
                mma_bf16(s[2*n16+1], qh[kc], kl4[2], kl4[3]);
                mma_bf16(s[2*n16+1], ql[kc], kh4[2], kh4[3]);
            }
        }

        if (nb < 7) { storeK(cur ^ 1); loadV(n0 + 128); }

        // srel: s[l][m] += qe[l][1023 + m - l]  for m <= l
        if (n0 <= m0) {
            const float* q0 = g_qe + ((size_t)bh * Lq + l0) * Lq + (1023 - l0);
            const float* q1 = g_qe + ((size_t)bh * Lq + l1) * Lq + (1023 - l1);
            #pragma unroll
            for (int f = 0; f < 16; f++) {
                int m = n0 + f * 8 + (lane & 3) * 2;
                if (m < l0)       { s[f][0] += q0[m]; s[f][1] += q0[m + 1]; }
                else if (m == l0) { s[f][0] += q0[m]; }
                if (m < l1)       { s[f][2] += q1[m]; s[f][3] += q1[m + 1]; }
                else if (m == l1) { s[f][2] += q1[m]; }
            }
        }

        // online softmax (quad-local rows)
        float mx0 = -3.4e38f, mx1 = -3.4e38f;
        #pragma unroll
        for (int f = 0; f < 16; f++) {
            mx0 = fmaxf(mx0, fmaxf(s[f][0], s[f][1]));
            mx1 = fmaxf(mx1, fmaxf(s[f][2], s[f][3]));
        }
        mx0 = fmaxf(mx0, __shfl_xor_sync(0xffffffffu, mx0, 1));
        mx0 = fmaxf(mx0, __shfl_xor_sync(0xffffffffu, mx0, 2));
        mx1 = fmaxf(mx1, __shfl_xor_sync(0xffffffffu, mx1, 1));
        mx1 = fmaxf(mx1, __shfl_xor_sync(0xffffffffu, mx1, 2));
        float nm0 = fmaxf(mst0, mx0), nm1 = fmaxf(mst1, mx1);
        float sc0 = exp2f((mst0 - nm0) * L2E), sc1 = exp2f((mst1 - nm1) * L2E);
        mst0 = nm0; mst1 = nm1;
        sum0 *= sc0; sum1 *= sc1;
        #pragma unroll
        for (int f = 0; f < 8; f++) {
            o[f][0] *= sc0; o[f][1] *= sc0; o[f][2] *= sc1; o[f][3] *= sc1;
        }
        #pragma unroll
        for (int f = 0; f < 16; f++) {
            s[f][0] = exp2f((s[f][0] - nm0) * L2E);
            s[f][1] = exp2f((s[f][1] - nm0) * L2E);
            s[f][2] = exp2f((s[f][2] - nm1) * L2E);
            s[f][3] = exp2f((s[f][3] - nm1) * L2E);
            sum0 += s[f][0] + s[f][1];
            sum1 += s[f][2] + s[f][3];
        }

        if (nb < 7) storeV(cur ^ 1);

        // O += P V  (split x3)
        #pragma unroll
        for (int kk = 0; kk < 8; kk++) {
            uint32_t ahp[4], alp[4];
            {
                float p00 = s[2*kk][0],   p01 = s[2*kk][1];
                float p10 = s[2*kk][2],   p11 = s[2*kk][3];
                float p20 = s[2*kk+1][0], p21 = s[2*kk+1][1];
                float p30 = s[2*kk+1][2], p31 = s[2*kk+1][3];
                ahp[0] = packbf(p00, p01); ahp[1] = packbf(p10, p11);
                ahp[2] = packbf(p20, p21); ahp[3] = packbf(p30, p31);
                __nv_bfloat162 h;
                h = *(__nv_bfloat162*)&ahp[0];
                alp[0] = packbf(p00 - __low2float(h), p01 - __high2float(h));
                h = *(__nv_bfloat162*)&ahp[1];
                alp[1] = packbf(p10 - __low2float(h), p11 - __high2float(h));
                h = *(__nv_bfloat162*)&ahp[2];
                alp[2] = packbf(p20 - __low2float(h), p21 - __high2float(h));
                h = *(__nv_bfloat162*)&ahp[3];
                alp[3] = packbf(p30 - __low2float(h), p31 - __high2float(h));
            }
            #pragma unroll
            for (int n16 = 0; n16 < 4; n16++) {
                uint32_t off = SWZ256((n16 * 16 + brow) * 256 + (kk * 16 + bk8) * 2);
                uint32_t vh4[4], vl4[4];
                ldsm4(vh4, suV + off); ldsm4(vl4, suVl + off);
                mma_bf16(o[2*n16],   ahp, vh4[0], vh4[1]);
                mma_bf16(o[2*n16],   ahp, vl4[0], vl4[1]);
                mma_bf16(o[2*n16],   alp, vh4[0], vh4[1]);
                mma_bf16(o[2*n16+1], ahp, vh4[2], vh4[3]);
                mma_bf16(o[2*n16+1], ahp, vl4[2], vl4[3]);
                mma_bf16(o[2*n16+1], alp, vh4[2], vh4[3]);
            }
        }
        __syncthreads();
    }

    // finalize
    sum0 += __shfl_xor_sync(0xffffffffu, sum0, 1);
    sum0 += __shfl_xor_sync(0xffffffffu, sum0, 2);
    sum1 += __shfl_xor_sync(0xffffffffu, sum1, 1);
    sum1 += __shfl_xor_sync(0xffffffffu, sum1, 2);
    const float inv0 = 1.0f / sum0, inv1 = 1.0f / sum1;
    const int b = bh >> 4, h = bh & 15;
    #pragma unroll
    for (int f = 0; f < 8; f++) {
        int d = f * 8 + (lane & 3) * 2;
        float2 v0 = make_float2(o[f][0] * inv0, o[f][1] * inv0);
        float2 v1 = make_float2(o[f][2] * inv1, o[f][3] * inv1);
        *(float2*)(g_ctx + (size_t)l0 * (Bq * Eq) + b * Eq + h * Dh + d) = v0;
        *(float2*)(g_ctx + (size_t)l1 * (Bq * Eq) + b * Eq + h * Dh + d) = v1;
    }
}

__global__ __launch_bounds__(256, 1) void k_outproj(const float* __restrict__ W,
                                                    const float* __restrict__ bias,
                                                    float* __restrict__ out) {
    int m0 = blockIdx.y * 128, n0 = blockIdx.x * 128;
    EpiBias e{out, bias, m0, n0};
    mm_main<128>(g_ctx + (size_t)m0 * Eq, Eq, W + (size_t)n0 * Eq, Eq, Eq, e);
}

// ---------------------------------------------------------------------------
extern "C" void kernel_launch(void* const* d_in, const int* in_sizes, int n_in,
                              void* d_out, int out_size)
{
    (void)in_sizes; (void)n_in; (void)out_size;
    const float* query  = (const float*)d_in[0];
    const float* relpos = (const float*)d_in[1];
    const float* w_in   = (const float*)d_in[2];
    const float* b_in   = (const float*)d_in[3];
    const float* w_out  = (const float*)d_in[4];
    const float* b_out  = (const float*)d_in[5];
    float* out = (float*)d_out;

    const int SMG = 2 * (16384 + 2 * 128 * 64);   // 65536 for NT=128
    cudaFuncSetAttribute(k_qkv,     cudaFuncAttributeMaxDynamicSharedMemorySize, SMG);
    cudaFuncSetAttribute(k_qe,      cudaFuncAttributeMaxDynamicSharedMemorySize, SMG);
    cudaFuncSetAttribute(k_outproj, cudaFuncAttributeMaxDynamicSharedMemorySize, SMG);
    cudaFuncSetAttribute(k_attn,    cudaFuncAttributeMaxDynamicSharedMemorySize, 131072);

    k_qkv    <<<dim3(24, 32),   256, SMG>>>(query, w_in, b_in);
    k_qe     <<<dim3(8, 8, 64), 256, SMG>>>(relpos);
    k_attn   <<<dim3(8, 64),    256, 131072>>>();
    k_outproj<<<dim3(8, 32),    256, SMG>>>(w_out, b_out, out);
}